// round 9
// baseline (speedup 1.0000x reference)
#include <cuda_runtime.h>
#include <cuda_bf16.h>

// ---------------------------------------------------------------------------
// G2EquivariantFeedForward, GB300 sm_103a — round 9
//
// Closed form: upd = a*x + b*x^2 + c*x^3 = (P, Q*v) for x = r + v,
//   P = a*r + b*(r^2-n^2) + c*r*(r^2-3n^2)
//   Q = a + 2*b*r + c*(3r^2-n^2),  n^2=|v|^2,  |upd|^2 = P^2 + Q^2 n^2
//
// Round 9 = round 8 (constant-port weights, 57.8us) with FOUR independent
// f32x2 streams per thread (8 octonions) to double ILP across the GELU
// dependency chain. __launch_bounds__(128,6) -> 85-reg budget, natural
// demand ~80, no clamp spills. OPB=1024 -> 4096 blocks exact.
// ---------------------------------------------------------------------------

typedef unsigned long long U64;

__device__ __forceinline__ U64 pk2(float lo, float hi) {
    U64 r; asm("mov.b64 %0, {%1, %2};" : "=l"(r) : "f"(lo), "f"(hi)); return r;
}
__device__ __forceinline__ void upk2(U64 v, float& lo, float& hi) {
    asm("mov.b64 {%0, %1}, %2;" : "=f"(lo), "=f"(hi) : "l"(v));
}
__device__ __forceinline__ U64 fma2(U64 a, U64 b, U64 c) {
    U64 d; asm("fma.rn.f32x2 %0, %1, %2, %3;" : "=l"(d) : "l"(a), "l"(b), "l"(c)); return d;
}
__device__ __forceinline__ U64 mul2(U64 a, U64 b) {
    U64 d; asm("mul.rn.f32x2 %0, %1, %2;" : "=l"(d) : "l"(a), "l"(b)); return d;
}
__device__ __forceinline__ U64 add2(U64 a, U64 b) {
    U64 d; asm("add.rn.f32x2 %0, %1, %2;" : "=l"(d) : "l"(a), "l"(b)); return d;
}
__device__ __forceinline__ float tanh_ap(float x) {
    float t; asm("tanh.approx.f32 %0, %1;" : "=f"(t) : "f"(x)); return t;
}
__device__ __forceinline__ float sqrt_ap(float x) {
    float t; asm("sqrt.approx.f32 %0, %1;" : "=f"(t) : "f"(x)); return t;
}
__device__ __forceinline__ float rsqrt_ap(float x) {
    float t; asm("rsqrt.approx.f32 %0, %1;" : "=f"(t) : "f"(x)); return t;
}

__device__ __forceinline__ float norm2_imag(const float4& a0, const float4& a1) {
    float n = a0.y * a0.y;
    n = fmaf(a0.z, a0.z, n);
    n = fmaf(a0.w, a0.w, n);
    n = fmaf(a1.x, a1.x, n);
    n = fmaf(a1.y, a1.y, n);
    n = fmaf(a1.z, a1.z, n);
    n = fmaf(a1.w, a1.w, n);
    return n;
}

// ---- packed weight tables: built on device, then copied into __constant__ ----
struct __align__(16) CTab {
    ulonglong2 W1[32];   // (w0,w0 | w1,w1)
    ulonglong2 BW[32];   // (b1,b1 | 0.5*w2c,0.5*w2c)
    ulonglong2 W2[32];   // (0.5*w2a,.. | 0.5*w2b,..)
    U64        B2[3];    // (b2k, b2k)
    float      scal[2];  // lam, 1-lam
};

__device__   CTab dScratch;   // written by prep kernel
__constant__ CTab cT;         // read by main kernel (constant port)

__global__ void prep_kernel(const float* __restrict__ W1,
                            const float* __restrict__ b1,
                            const float* __restrict__ W2,
                            const float* __restrict__ b2,
                            const float* __restrict__ alpha)
{
    const int t = threadIdx.x;     // 32 threads
    float w0 = W1[2 * t], w1 = W1[2 * t + 1];
    ulonglong2 q; q.x = pk2(w0, w0); q.y = pk2(w1, w1);
    dScratch.W1[t] = q;
    float bb = b1[t], wc = 0.5f * W2[64 + t];
    ulonglong2 qb; qb.x = pk2(bb, bb); qb.y = pk2(wc, wc);
    dScratch.BW[t] = qb;
    float wa = 0.5f * W2[t], wb = 0.5f * W2[32 + t];
    ulonglong2 q2; q2.x = pk2(wa, wa); q2.y = pk2(wb, wb);
    dScratch.W2[t] = q2;
    if (t == 0) {
        float al  = alpha[0];
        float lam = 1.0f / (1.0f + __expf(-al));
        dScratch.scal[0] = lam;
        dScratch.scal[1] = 1.0f - lam;
        dScratch.B2[0] = pk2(b2[0], b2[0]);
        dScratch.B2[1] = pk2(b2[1], b2[1]);
        dScratch.B2[2] = pk2(b2[2], b2[2]);
    }
}

#define TPB 128          // threads per block
#define NS  4            // streams per thread (2 octonions each)
#define OPB (TPB * 2 * NS)   // 1024 octonions per block

__global__ __launch_bounds__(TPB, 6)
void g2ff_kernel(const float4* __restrict__ in4,
                 float4*       __restrict__ out4)
{
    const int t = threadIdx.x;
    const int base = blockIdx.x * OPB;

    // stream s packs octonions (base + 2s*TPB + t, base + (2s+1)*TPB + t)
    int mLo[NS], mHi[NS];
#pragma unroll
    for (int s = 0; s < NS; s++) {
        mLo[s] = base + (2 * s)     * TPB + t;
        mHi[s] = base + (2 * s + 1) * TPB + t;
    }

    // ---- prologue: scalar n^2 per octonion; pack (r, np) pairs ----
    U64 p0[NS], np[NS];
#pragma unroll
    for (int s = 0; s < NS; s++) {
        float4 a0 = in4[2 * mLo[s] + 0];
        float4 a1 = in4[2 * mLo[s] + 1];
        float4 b0 = in4[2 * mHi[s] + 0];
        float4 b1v = in4[2 * mHi[s] + 1];
        float nA = norm2_imag(a0, a1);
        float nB = norm2_imag(b0, b1v);
        p0[s] = pk2(a0.x, b0.x);
        np[s] = pk2(sqrt_ap(nA), sqrt_ap(nB));
    }

    // GELU-tanh constants
    const U64 C1 = pk2(0.7978845608028654f, 0.7978845608028654f);
    const U64 C2 = pk2(0.035677408136300125f, 0.035677408136300125f);

    U64 aA[NS], aB[NS], aC[NS];
#pragma unroll
    for (int s = 0; s < NS; s++) {
        aA[s] = cT.B2[0];
        aB[s] = cT.B2[1];
        aC[s] = cT.B2[2];
    }

#pragma unroll
    for (int j = 0; j < 32; j++) {
        ulonglong2 w1j = cT.W1[j];   // constant port (off L1tex)
        ulonglong2 bwj = cT.BW[j];
        ulonglong2 w2j = cT.W2[j];

#pragma unroll
        for (int s = 0; s < NS; s++) {
            // h' = z*(1+tanh(u)) = 2*gelu(z); W2 tables pre-halved
            U64 z  = fma2(np[s], w1j.y, fma2(p0[s], w1j.x, bwj.x));
            U64 z2 = mul2(z, z);
            U64 qq = fma2(z2, C2, C1);
            U64 u  = mul2(z, qq);
            float ul, uh; upk2(u, ul, uh);
            U64 tt = pk2(tanh_ap(ul), tanh_ap(uh));
            U64 h  = fma2(z, tt, z);
            aA[s] = fma2(h, w2j.x, aA[s]);
            aB[s] = fma2(h, w2j.y, aB[s]);
            aC[s] = fma2(h, bwj.y, aC[s]);
        }
    }

    const U64 N1  = pk2(-1.0f, -1.0f);
    const U64 N3  = pk2(-3.0f, -3.0f);
    const U64 TWO = pk2(2.0f, 2.0f);

    const float lam = cT.scal[0], oml = cT.scal[1];
    const U64 LAM = pk2(lam, lam);
    const U64 OML = pk2(oml, oml);

    // ---- epilogue per stream (re-load octonions from global; L2 hit) ----
#pragma unroll
    for (int s = 0; s < NS; s++) {
        U64 n2 = mul2(np[s], np[s]);          // recompute (np = sqrt(n2))
        U64 r2 = mul2(p0[s], p0[s]);
        U64 s2 = fma2(n2, N1, r2);            // r^2 - n^2
        U64 u3 = fma2(n2, N3, r2);            // r^2 - 3n^2
        U64 s3 = mul2(p0[s], u3);
        U64 t3 = fma2(r2, TWO, s2);           // 3r^2 - n^2
        U64 P  = fma2(aA[s], p0[s], fma2(aB[s], s2, mul2(aC[s], s3)));
        U64 tr = add2(p0[s], p0[s]);
        U64 Q  = fma2(aC[s], t3, fma2(aB[s], tr, aA[s]));
        U64 ss = fma2(mul2(Q, Q), n2, mul2(P, P));
        float sl, sh; upk2(ss, sl, sh);
        sl = fmaxf(sl, 1e-16f);
        sh = fmaxf(sh, 1e-16f);
        U64 inv = pk2(rsqrt_ap(sl), rsqrt_ap(sh));
        U64 li  = mul2(LAM, inv);
        U64 K   = fma2(li, Q, OML);
        U64 o0  = fma2(li, P, mul2(p0[s], OML));

        float Klo, Khi; upk2(K, Klo, Khi);
        float olo, ohi; upk2(o0, olo, ohi);

        float4 a0 = in4[2 * mLo[s] + 0];
        float4 a1 = in4[2 * mLo[s] + 1];
        a0.x = olo;
        a0.y *= Klo; a0.z *= Klo; a0.w *= Klo;
        a1.x *= Klo; a1.y *= Klo; a1.z *= Klo; a1.w *= Klo;
        out4[2 * mLo[s] + 0] = a0;
        out4[2 * mLo[s] + 1] = a1;

        float4 b0 = in4[2 * mHi[s] + 0];
        float4 b1v = in4[2 * mHi[s] + 1];
        b0.x = ohi;
        b0.y *= Khi; b0.z *= Khi; b0.w *= Khi;
        b1v.x *= Khi; b1v.y *= Khi; b1v.z *= Khi; b1v.w *= Khi;
        out4[2 * mHi[s] + 0] = b0;
        out4[2 * mHi[s] + 1] = b1v;
    }
}

extern "C" void kernel_launch(void* const* d_in, const int* in_sizes, int n_in,
                              void* d_out, int out_size)
{
    const float* o     = (const float*)d_in[0];
    const float* W1    = (const float*)d_in[1];
    const float* b1    = (const float*)d_in[2];
    const float* W2    = (const float*)d_in[3];
    const float* b2    = (const float*)d_in[4];
    const float* alpha = (const float*)d_in[5];

    // 1) pack weight tables on device
    prep_kernel<<<1, 32>>>(W1, b1, W2, b2, alpha);

    // 2) copy packed tables into __constant__ (D2D memcpy node, capturable)
    void* scratch_addr = nullptr;
    cudaGetSymbolAddress(&scratch_addr, dScratch);
    cudaMemcpyToSymbolAsync(cT, scratch_addr, sizeof(CTab), 0,
                            cudaMemcpyDeviceToDevice);

    // 3) main kernel
    const int total = in_sizes[0];          // 33,554,432 floats
    const int octs  = total / 8;            // 4,194,304 octonions
    const int blocks = octs / OPB;          // 4096

    g2ff_kernel<<<blocks, TPB>>>((const float4*)o, (float4*)d_out);
}

// round 10
// speedup vs baseline: 1.1072x; 1.1072x over previous
#include <cuda_runtime.h>
#include <cuda_bf16.h>

// ---------------------------------------------------------------------------
// G2EquivariantFeedForward, GB300 sm_103a — round 10
//
// Closed form: upd = a*x + b*x^2 + c*x^3 = (P, Q*v) for x = r + v,
//   P = a*r + b*(r^2-n^2) + c*r*(r^2-3n^2)
//   Q = a + 2*b*r + c*(3r^2-n^2),  n^2=|v|^2,  |upd|^2 = P^2 + Q^2 n^2
//
// Round 10: TLP over ILP (round 9 proved ILP loses to occupancy here).
// ONE f32x2 stream per thread (2 octonions), minimal register footprint
// (~42 regs) -> ~70% occupancy. Constant-port weight tables (round 8 win)
// unchanged: prep kernel packs -> cudaMemcpyToSymbolAsync -> LDC in loop.
// ---------------------------------------------------------------------------

typedef unsigned long long U64;

__device__ __forceinline__ U64 pk2(float lo, float hi) {
    U64 r; asm("mov.b64 %0, {%1, %2};" : "=l"(r) : "f"(lo), "f"(hi)); return r;
}
__device__ __forceinline__ void upk2(U64 v, float& lo, float& hi) {
    asm("mov.b64 {%0, %1}, %2;" : "=f"(lo), "=f"(hi) : "l"(v));
}
__device__ __forceinline__ U64 fma2(U64 a, U64 b, U64 c) {
    U64 d; asm("fma.rn.f32x2 %0, %1, %2, %3;" : "=l"(d) : "l"(a), "l"(b), "l"(c)); return d;
}
__device__ __forceinline__ U64 mul2(U64 a, U64 b) {
    U64 d; asm("mul.rn.f32x2 %0, %1, %2;" : "=l"(d) : "l"(a), "l"(b)); return d;
}
__device__ __forceinline__ U64 add2(U64 a, U64 b) {
    U64 d; asm("add.rn.f32x2 %0, %1, %2;" : "=l"(d) : "l"(a), "l"(b)); return d;
}
__device__ __forceinline__ float tanh_ap(float x) {
    float t; asm("tanh.approx.f32 %0, %1;" : "=f"(t) : "f"(x)); return t;
}
__device__ __forceinline__ float sqrt_ap(float x) {
    float t; asm("sqrt.approx.f32 %0, %1;" : "=f"(t) : "f"(x)); return t;
}
__device__ __forceinline__ float rsqrt_ap(float x) {
    float t; asm("rsqrt.approx.f32 %0, %1;" : "=f"(t) : "f"(x)); return t;
}

__device__ __forceinline__ float norm2_imag(const float4& a0, const float4& a1) {
    float n = a0.y * a0.y;
    n = fmaf(a0.z, a0.z, n);
    n = fmaf(a0.w, a0.w, n);
    n = fmaf(a1.x, a1.x, n);
    n = fmaf(a1.y, a1.y, n);
    n = fmaf(a1.z, a1.z, n);
    n = fmaf(a1.w, a1.w, n);
    return n;
}

// ---- packed weight tables: built on device, then copied into __constant__ ----
struct __align__(16) CTab {
    ulonglong2 W1[32];   // (w0,w0 | w1,w1)
    ulonglong2 BW[32];   // (b1,b1 | 0.5*w2c,0.5*w2c)
    ulonglong2 W2[32];   // (0.5*w2a,.. | 0.5*w2b,..)
    U64        B2[3];    // (b2k, b2k)
    float      scal[2];  // lam, 1-lam
};

__device__   CTab dScratch;   // written by prep kernel
__constant__ CTab cT;         // read by main kernel (constant port)

__global__ void prep_kernel(const float* __restrict__ W1,
                            const float* __restrict__ b1,
                            const float* __restrict__ W2,
                            const float* __restrict__ b2,
                            const float* __restrict__ alpha)
{
    const int t = threadIdx.x;     // 32 threads
    float w0 = W1[2 * t], w1 = W1[2 * t + 1];
    ulonglong2 q; q.x = pk2(w0, w0); q.y = pk2(w1, w1);
    dScratch.W1[t] = q;
    float bb = b1[t], wc = 0.5f * W2[64 + t];
    ulonglong2 qb; qb.x = pk2(bb, bb); qb.y = pk2(wc, wc);
    dScratch.BW[t] = qb;
    float wa = 0.5f * W2[t], wb = 0.5f * W2[32 + t];
    ulonglong2 q2; q2.x = pk2(wa, wa); q2.y = pk2(wb, wb);
    dScratch.W2[t] = q2;
    if (t == 0) {
        float al  = alpha[0];
        float lam = 1.0f / (1.0f + __expf(-al));
        dScratch.scal[0] = lam;
        dScratch.scal[1] = 1.0f - lam;
        dScratch.B2[0] = pk2(b2[0], b2[0]);
        dScratch.B2[1] = pk2(b2[1], b2[1]);
        dScratch.B2[2] = pk2(b2[2], b2[2]);
    }
}

#define TPB 128          // threads per block
#define OPB (TPB * 2)    // 256 octonions per block (2 per thread)

__global__ __launch_bounds__(TPB, 11)
void g2ff_kernel(const float4* __restrict__ in4,
                 float4*       __restrict__ out4)
{
    const int t = threadIdx.x;
    const int base = blockIdx.x * OPB;
    const int mLo = base + t;          // low-lane octonion
    const int mHi = base + TPB + t;    // high-lane octonion

    // ---- prologue: scalar n^2 per octonion; pack (r, np) pair ----
    U64 p0, np;
    {
        float4 a0 = in4[2 * mLo + 0];
        float4 a1 = in4[2 * mLo + 1];
        float4 b0 = in4[2 * mHi + 0];
        float4 b1v = in4[2 * mHi + 1];
        float nA = norm2_imag(a0, a1);
        float nB = norm2_imag(b0, b1v);
        p0 = pk2(a0.x, b0.x);
        np = pk2(sqrt_ap(nA), sqrt_ap(nB));
    }

    // GELU-tanh constants
    const U64 C1 = pk2(0.7978845608028654f, 0.7978845608028654f);
    const U64 C2 = pk2(0.035677408136300125f, 0.035677408136300125f);

    U64 aA = cT.B2[0], aB = cT.B2[1], aC = cT.B2[2];

#pragma unroll
    for (int j = 0; j < 32; j++) {
        ulonglong2 w1j = cT.W1[j];   // constant port (off L1tex)
        ulonglong2 bwj = cT.BW[j];
        ulonglong2 w2j = cT.W2[j];

        // h' = z*(1+tanh(u)) = 2*gelu(z); W2 tables pre-halved
        U64 z  = fma2(np, w1j.y, fma2(p0, w1j.x, bwj.x));
        U64 z2 = mul2(z, z);
        U64 qq = fma2(z2, C2, C1);
        U64 u  = mul2(z, qq);
        float ul, uh; upk2(u, ul, uh);
        U64 tt = pk2(tanh_ap(ul), tanh_ap(uh));
        U64 h  = fma2(z, tt, z);
        aA = fma2(h, w2j.x, aA);
        aB = fma2(h, w2j.y, aB);
        aC = fma2(h, bwj.y, aC);
    }

    const U64 N1  = pk2(-1.0f, -1.0f);
    const U64 N3  = pk2(-3.0f, -3.0f);
    const U64 TWO = pk2(2.0f, 2.0f);

    const float lam = cT.scal[0], oml = cT.scal[1];
    const U64 LAM = pk2(lam, lam);
    const U64 OML = pk2(oml, oml);

    // ---- epilogue (re-load octonions from global; L2 hit) ----
    U64 n2 = mul2(np, np);                // recompute (np = sqrt(n2))
    U64 r2 = mul2(p0, p0);
    U64 s2 = fma2(n2, N1, r2);            // r^2 - n^2
    U64 u3 = fma2(n2, N3, r2);            // r^2 - 3n^2
    U64 s3 = mul2(p0, u3);
    U64 t3 = fma2(r2, TWO, s2);           // 3r^2 - n^2
    U64 P  = fma2(aA, p0, fma2(aB, s2, mul2(aC, s3)));
    U64 tr = add2(p0, p0);
    U64 Q  = fma2(aC, t3, fma2(aB, tr, aA));
    U64 ss = fma2(mul2(Q, Q), n2, mul2(P, P));
    float sl, sh; upk2(ss, sl, sh);
    sl = fmaxf(sl, 1e-16f);
    sh = fmaxf(sh, 1e-16f);
    U64 inv = pk2(rsqrt_ap(sl), rsqrt_ap(sh));
    U64 li  = mul2(LAM, inv);
    U64 K   = fma2(li, Q, OML);
    U64 o0  = fma2(li, P, mul2(p0, OML));

    float Klo, Khi; upk2(K, Klo, Khi);
    float olo, ohi; upk2(o0, olo, ohi);

    {
        float4 a0 = in4[2 * mLo + 0];
        float4 a1 = in4[2 * mLo + 1];
        a0.x = olo;
        a0.y *= Klo; a0.z *= Klo; a0.w *= Klo;
        a1.x *= Klo; a1.y *= Klo; a1.z *= Klo; a1.w *= Klo;
        out4[2 * mLo + 0] = a0;
        out4[2 * mLo + 1] = a1;
    }
    {
        float4 b0 = in4[2 * mHi + 0];
        float4 b1v = in4[2 * mHi + 1];
        b0.x = ohi;
        b0.y *= Khi; b0.z *= Khi; b0.w *= Khi;
        b1v.x *= Khi; b1v.y *= Khi; b1v.z *= Khi; b1v.w *= Khi;
        out4[2 * mHi + 0] = b0;
        out4[2 * mHi + 1] = b1v;
    }
}

extern "C" void kernel_launch(void* const* d_in, const int* in_sizes, int n_in,
                              void* d_out, int out_size)
{
    const float* o     = (const float*)d_in[0];
    const float* W1    = (const float*)d_in[1];
    const float* b1    = (const float*)d_in[2];
    const float* W2    = (const float*)d_in[3];
    const float* b2    = (const float*)d_in[4];
    const float* alpha = (const float*)d_in[5];

    // 1) pack weight tables on device
    prep_kernel<<<1, 32>>>(W1, b1, W2, b2, alpha);

    // 2) copy packed tables into __constant__ (D2D memcpy node, capturable)
    void* scratch_addr = nullptr;
    cudaGetSymbolAddress(&scratch_addr, dScratch);
    cudaMemcpyToSymbolAsync(cT, scratch_addr, sizeof(CTab), 0,
                            cudaMemcpyDeviceToDevice);

    // 3) main kernel
    const int total = in_sizes[0];          // 33,554,432 floats
    const int octs  = total / 8;            // 4,194,304 octonions
    const int blocks = octs / OPB;          // 16384

    g2ff_kernel<<<blocks, TPB>>>((const float4*)o, (float4*)d_out);
}